// round 13
// baseline (speedup 1.0000x reference)
#include <cuda_runtime.h>
#include <cstdint>

#define Bsz  16384
#define Gn   128
#define Sn   64
#define Hn   10
#define PHn  100

typedef unsigned long long ull;

// scratch: gene_layer stored transposed [G][B]
__device__ float g_GL[(size_t)Gn * Bsz];

// ---------------- packed f32x2 helpers (sm_103a) ----------------
__device__ __forceinline__ ull ffma2(ull a, ull b, ull c) {
    ull d;
    asm("fma.rn.f32x2 %0, %1, %2, %3;" : "=l"(d) : "l"(a), "l"(b), "l"(c));
    return d;
}
__device__ __forceinline__ ull add2(ull a, ull b) {
    ull d;
    asm("add.rn.f32x2 %0, %1, %2;" : "=l"(d) : "l"(a), "l"(b));
    return d;
}
__device__ __forceinline__ ull dup2(float x) {
    ull r;
    asm("mov.b64 %0, {%1, %1};" : "=l"(r) : "f"(x));
    return r;
}
__device__ __forceinline__ void unpack2(ull v, float& lo, float& hi) {
    asm("mov.b64 {%0, %1}, %2;" : "=f"(lo), "=f"(hi) : "l"(v));
}

// =======================================================================
// Stage 1: per-gene MLP, 4 lanes/row, 2 rows/thread.  Depth-2 register
//   pipeline: 3 rotating buffers, 8-pass loop fully unrolled (static idx).
//   grid = (G, B/ROWS1), block = 128
// =======================================================================
#define TH1     128
#define ROWS1   512
#define PASS1   8

__global__ void __launch_bounds__(TH1)
stage1_kernel(const float* __restrict__ x,
              const float* __restrict__ W1,
              const float* __restrict__ b1,
              const float* __restrict__ W2,
              const float* __restrict__ b2)
{
    __shared__ ull  ws[4 * 82 + 8];
    __shared__ float w2s[10];
    __shared__ float b2s;

    const int g   = blockIdx.x;
    const int tid = threadIdx.x;

    const ull* W1u = reinterpret_cast<const ull*>(W1 + (size_t)g * Sn * Hn);
    for (int p = tid; p < Sn * (Hn / 2); p += TH1) {
        int s = p / 5, hp = p % 5;
        int j = (s >> 2) & 3;
        int k = s >> 4;
        int i = s & 3;
        ws[j * 82 + (k * 4 + i) * 5 + hp] = W1u[p];
    }
    if (tid < 5)  ws[4 * 82 + tid] = reinterpret_cast<const ull*>(b1 + g * Hn)[tid];
    if (tid < 10) w2s[tid] = W2[g * Hn + tid];
    if (tid == 0) b2s = b2[g];
    __syncthreads();

    const int w    = tid >> 5;
    const int lane = tid & 31;
    const int rg   = lane >> 2;
    const int j2   = lane & 3;
    const ull* wsl = ws + j2 * 82;

    ull b1r[5];
#pragma unroll
    for (int hp = 0; hp < 5; hp++) b1r[hp] = ws[4 * 82 + hp];
    float w2r[10];
#pragma unroll
    for (int h = 0; h < 10; h++) w2r[h] = w2s[h];
    const float b2v = b2s;

    const int rowbase = blockIdx.y * ROWS1 + w * 16 + rg;
    const float4* x4 = reinterpret_cast<const float4*>(x);
    const size_t gidx = (size_t)rowbase * 2048 + (size_t)g * 16 + j2;
    // pass p load index: gidx + p*64*2048 ; B row at +8*2048

    float4 bufA[3][4], bufB[3][4];

    // prologue: fill buffers for pass 0 and pass 1
#pragma unroll
    for (int s = 0; s < 2; s++) {
        const size_t ip = gidx + (size_t)s * 131072;
#pragma unroll
        for (int k = 0; k < 4; k++) {
            bufA[s][k] = x4[ip + k * 4];
            bufB[s][k] = x4[ip + 16384 + k * 4];
        }
    }

#pragma unroll
    for (int pass = 0; pass < PASS1; pass++) {
        const int cur = pass % 3;
        const int nxt = (pass + 2) % 3;

        // issue loads for pass+2 (depth-2 window)
        if (pass + 2 < PASS1) {
            const size_t ip = gidx + (size_t)(pass + 2) * 131072;
#pragma unroll
            for (int k = 0; k < 4; k++) {
                bufA[nxt][k] = x4[ip + k * 4];
                bufB[nxt][k] = x4[ip + 16384 + k * 4];
            }
        }

        // ---- compute pass ----
        ull accA[5], accB[5];
#pragma unroll
        for (int hp = 0; hp < 5; hp++) { accA[hp] = 0ull; accB[hp] = 0ull; }

#pragma unroll
        for (int k = 0; k < 4; k++) {
            float fa[4] = {bufA[cur][k].x, bufA[cur][k].y, bufA[cur][k].z, bufA[cur][k].w};
            float fb[4] = {bufB[cur][k].x, bufB[cur][k].y, bufB[cur][k].z, bufB[cur][k].w};
#pragma unroll
            for (int i = 0; i < 4; i++) {
                ull a2 = dup2(fa[i]);
                ull c2 = dup2(fb[i]);
                const ull* wrow = wsl + (k * 4 + i) * 5;
#pragma unroll
                for (int hp = 0; hp < 5; hp++) {
                    ull wv = wrow[hp];
                    accA[hp] = ffma2(a2, wv, accA[hp]);
                    accB[hp] = ffma2(c2, wv, accB[hp]);
                }
            }
        }

#pragma unroll
        for (int off = 1; off <= 2; off <<= 1) {
#pragma unroll
            for (int hp = 0; hp < 5; hp++) {
                accA[hp] = add2(accA[hp], __shfl_xor_sync(0xffffffffu, accA[hp], off));
                accB[hp] = add2(accB[hp], __shfl_xor_sync(0xffffffffu, accB[hp], off));
            }
        }

        float glA = b2v, glB = b2v;
#pragma unroll
        for (int hp = 0; hp < 5; hp++) {
            float l, h;
            unpack2(add2(accA[hp], b1r[hp]), l, h);
            glA += fmaxf(l, 0.f) * w2r[2 * hp] + fmaxf(h, 0.f) * w2r[2 * hp + 1];
            unpack2(add2(accB[hp], b1r[hp]), l, h);
            glB += fmaxf(l, 0.f) * w2r[2 * hp] + fmaxf(h, 0.f) * w2r[2 * hp + 1];
        }
        const int rA = rowbase + pass * 64;
        if (j2 == 0) {
            g_GL[(size_t)g * Bsz + rA]     = glA;
            g_GL[(size_t)g * Bsz + rA + 8] = glB;
        }
    }
}

// =======================================================================
// Stage 2: register-tiled GEMM [B x G] @ [G x PH], thread tile 2 rows x 14
//   cols (PH zero-padded 100->112).  block = 128 (16 rowg x 8 colg),
//   Mtile = 32 rows, grid = 512 CTAs.  gl loads double-buffered.
// =======================================================================
#define TH2    128
#define MT2    32
#define PHP    112
#define SMEM2_FLOATS (Gn * PHP + PHP + PHP + 8 * MT2)
#define SMEM2_BYTES  (SMEM2_FLOATS * 4)     // 58368

__global__ void __launch_bounds__(TH2)
stage2_kernel(const float* __restrict__ Wp1,
              const float* __restrict__ bp1,
              const float* __restrict__ Wp2,
              const float* __restrict__ bp2,
              float* __restrict__ out)
{
    extern __shared__ float sm[];
    float* wp   = sm;                    // [G][PHP], zero-padded
    float* bp1p = sm + Gn * PHP;         // [PHP]
    float* wp2p = bp1p + PHP;            // [PHP]
    float* part = wp2p + PHP;            // [8][MT2]

    const int tid = threadIdx.x;

    for (int i = tid; i < Gn * PHP; i += TH2) {
        int gg = i / PHP, c = i - gg * PHP;
        wp[i] = (c < PHn) ? Wp1[gg * PHn + c] : 0.f;
    }
    if (tid < PHP) {
        bp1p[tid] = (tid < PHn) ? bp1[tid] : 0.f;
        wp2p[tid] = (tid < PHn) ? Wp2[tid] : 0.f;
    }
    __syncthreads();

    const int rowg = tid & 15;          // 16 row-groups of 2 rows
    const int cg   = tid >> 4;          // 8 col-groups of 14 cols
    const int b0   = blockIdx.x * MT2 + rowg * 2;

    ull acc[2][7];
    {
        const ull* bs = reinterpret_cast<const ull*>(bp1p + cg * 14);
#pragma unroll
        for (int q = 0; q < 7; q++) {
            ull v = bs[q];
            acc[0][q] = v;
            acc[1][q] = v;
        }
    }

    const float* glp = g_GL + b0;

    // double-buffered gl chunks of 4 genes
    float2 gcur[4], gnxt[4];
#pragma unroll
    for (int j = 0; j < 4; j++)
        gcur[j] = *reinterpret_cast<const float2*>(glp + (size_t)j * Bsz);

#pragma unroll 1
    for (int g0 = 0; g0 < Gn; g0 += 4) {
        if (g0 + 4 < Gn) {
#pragma unroll
            for (int j = 0; j < 4; j++)
                gnxt[j] = *reinterpret_cast<const float2*>(glp + (size_t)(g0 + 4 + j) * Bsz);
        }

#pragma unroll
        for (int j = 0; j < 4; j++) {
            const ull* wr = reinterpret_cast<const ull*>(wp + (g0 + j) * PHP + cg * 14);
            ull wv[7];
#pragma unroll
            for (int q = 0; q < 7; q++) wv[q] = wr[q];

            ull a0 = dup2(gcur[j].x);
            ull a1 = dup2(gcur[j].y);
#pragma unroll
            for (int q = 0; q < 7; q++) {
                acc[0][q] = ffma2(a0, wv[q], acc[0][q]);
                acc[1][q] = ffma2(a1, wv[q], acc[1][q]);
            }
        }
#pragma unroll
        for (int j = 0; j < 4; j++) gcur[j] = gnxt[j];
    }

    // epilogue: relu + dot with Wp2 slice, write partials
    {
        const ull* w2u = reinterpret_cast<const ull*>(wp2p + cg * 14);
        ull w2r[7];
#pragma unroll
        for (int q = 0; q < 7; q++) w2r[q] = w2u[q];
#pragma unroll
        for (int r = 0; r < 2; r++) {
            float y = 0.f;
#pragma unroll
            for (int q = 0; q < 7; q++) {
                float l, h, wl, wh;
                unpack2(acc[r][q], l, h);
                unpack2(w2r[q], wl, wh);
                y += fmaxf(l, 0.f) * wl + fmaxf(h, 0.f) * wh;
            }
            part[cg * MT2 + rowg * 2 + r] = y;
        }
    }
    __syncthreads();

    if (tid < MT2) {
        float s = bp2[0];
#pragma unroll
        for (int c = 0; c < 8; c++) s += part[c * MT2 + tid];
        out[blockIdx.x * MT2 + tid] = s;
    }
}

// =======================================================================
extern "C" void kernel_launch(void* const* d_in, const int* in_sizes, int n_in,
                              void* d_out, int out_size)
{
    const float* x   = (const float*)d_in[0];
    const float* W1  = (const float*)d_in[1];
    const float* b1  = (const float*)d_in[2];
    const float* W2  = (const float*)d_in[3];
    const float* b2  = (const float*)d_in[4];
    const float* Wp1 = (const float*)d_in[5];
    const float* bp1 = (const float*)d_in[6];
    const float* Wp2 = (const float*)d_in[7];
    const float* bp2 = (const float*)d_in[8];
    float* out = (float*)d_out;

    cudaFuncSetAttribute(stage2_kernel,
                         cudaFuncAttributeMaxDynamicSharedMemorySize, SMEM2_BYTES);

    dim3 grid1(Gn, Bsz / ROWS1);
    stage1_kernel<<<grid1, TH1>>>(x, W1, b1, W2, b2);
    stage2_kernel<<<Bsz / MT2, TH2, SMEM2_BYTES>>>(Wp1, bp1, Wp2, bp2, out);
}

// round 15
// speedup vs baseline: 1.0459x; 1.0459x over previous
#include <cuda_runtime.h>
#include <cstdint>

#define Bsz  16384
#define Gn   128
#define Sn   64
#define Hn   10
#define PHn  100

typedef unsigned long long ull;

// scratch: gene_layer stored transposed [G][B]
__device__ float g_GL[(size_t)Gn * Bsz];

// ---------------- packed f32x2 helpers (sm_103a) ----------------
__device__ __forceinline__ ull ffma2(ull a, ull b, ull c) {
    ull d;
    asm("fma.rn.f32x2 %0, %1, %2, %3;" : "=l"(d) : "l"(a), "l"(b), "l"(c));
    return d;
}
__device__ __forceinline__ ull add2(ull a, ull b) {
    ull d;
    asm("add.rn.f32x2 %0, %1, %2;" : "=l"(d) : "l"(a), "l"(b));
    return d;
}
__device__ __forceinline__ ull dup2(float x) {
    ull r;
    asm("mov.b64 %0, {%1, %1};" : "=l"(r) : "f"(x));
    return r;
}
__device__ __forceinline__ void unpack2(ull v, float& lo, float& hi) {
    asm("mov.b64 {%0, %1}, %2;" : "=f"(lo), "=f"(hi) : "l"(v));
}

// =======================================================================
// Stage 1 (R13 best, ~117us): per-gene MLP, 4 lanes/row, 2 rows/thread.
//   Depth-2 register pipeline, 3 rotating buffers, fully unrolled.
//   grid = (G, B/ROWS1), block = 128
// =======================================================================
#define TH1     128
#define ROWS1   512
#define PASS1   8

__global__ void __launch_bounds__(TH1)
stage1_kernel(const float* __restrict__ x,
              const float* __restrict__ W1,
              const float* __restrict__ b1,
              const float* __restrict__ W2,
              const float* __restrict__ b2)
{
    __shared__ ull  ws[4 * 82 + 8];
    __shared__ float w2s[10];
    __shared__ float b2s;

    const int g   = blockIdx.x;
    const int tid = threadIdx.x;

    const ull* W1u = reinterpret_cast<const ull*>(W1 + (size_t)g * Sn * Hn);
    for (int p = tid; p < Sn * (Hn / 2); p += TH1) {
        int s = p / 5, hp = p % 5;
        int j = (s >> 2) & 3;
        int k = s >> 4;
        int i = s & 3;
        ws[j * 82 + (k * 4 + i) * 5 + hp] = W1u[p];
    }
    if (tid < 5)  ws[4 * 82 + tid] = reinterpret_cast<const ull*>(b1 + g * Hn)[tid];
    if (tid < 10) w2s[tid] = W2[g * Hn + tid];
    if (tid == 0) b2s = b2[g];
    __syncthreads();

    const int w    = tid >> 5;
    const int lane = tid & 31;
    const int rg   = lane >> 2;
    const int j2   = lane & 3;
    const ull* wsl = ws + j2 * 82;

    ull b1r[5];
#pragma unroll
    for (int hp = 0; hp < 5; hp++) b1r[hp] = ws[4 * 82 + hp];
    float w2r[10];
#pragma unroll
    for (int h = 0; h < 10; h++) w2r[h] = w2s[h];
    const float b2v = b2s;

    const int rowbase = blockIdx.y * ROWS1 + w * 16 + rg;
    const float4* x4 = reinterpret_cast<const float4*>(x);
    const size_t gidx = (size_t)rowbase * 2048 + (size_t)g * 16 + j2;

    float4 bufA[3][4], bufB[3][4];

#pragma unroll
    for (int s = 0; s < 2; s++) {
        const size_t ip = gidx + (size_t)s * 131072;
#pragma unroll
        for (int k = 0; k < 4; k++) {
            bufA[s][k] = x4[ip + k * 4];
            bufB[s][k] = x4[ip + 16384 + k * 4];
        }
    }

#pragma unroll
    for (int pass = 0; pass < PASS1; pass++) {
        const int cur = pass % 3;
        const int nxt = (pass + 2) % 3;

        if (pass + 2 < PASS1) {
            const size_t ip = gidx + (size_t)(pass + 2) * 131072;
#pragma unroll
            for (int k = 0; k < 4; k++) {
                bufA[nxt][k] = x4[ip + k * 4];
                bufB[nxt][k] = x4[ip + 16384 + k * 4];
            }
        }

        ull accA[5], accB[5];
#pragma unroll
        for (int hp = 0; hp < 5; hp++) { accA[hp] = 0ull; accB[hp] = 0ull; }

#pragma unroll
        for (int k = 0; k < 4; k++) {
            float fa[4] = {bufA[cur][k].x, bufA[cur][k].y, bufA[cur][k].z, bufA[cur][k].w};
            float fb[4] = {bufB[cur][k].x, bufB[cur][k].y, bufB[cur][k].z, bufB[cur][k].w};
#pragma unroll
            for (int i = 0; i < 4; i++) {
                ull a2 = dup2(fa[i]);
                ull c2 = dup2(fb[i]);
                const ull* wrow = wsl + (k * 4 + i) * 5;
#pragma unroll
                for (int hp = 0; hp < 5; hp++) {
                    ull wv = wrow[hp];
                    accA[hp] = ffma2(a2, wv, accA[hp]);
                    accB[hp] = ffma2(c2, wv, accB[hp]);
                }
            }
        }

#pragma unroll
        for (int off = 1; off <= 2; off <<= 1) {
#pragma unroll
            for (int hp = 0; hp < 5; hp++) {
                accA[hp] = add2(accA[hp], __shfl_xor_sync(0xffffffffu, accA[hp], off));
                accB[hp] = add2(accB[hp], __shfl_xor_sync(0xffffffffu, accB[hp], off));
            }
        }

        float glA = b2v, glB = b2v;
#pragma unroll
        for (int hp = 0; hp < 5; hp++) {
            float l, h;
            unpack2(add2(accA[hp], b1r[hp]), l, h);
            glA += fmaxf(l, 0.f) * w2r[2 * hp] + fmaxf(h, 0.f) * w2r[2 * hp + 1];
            unpack2(add2(accB[hp], b1r[hp]), l, h);
            glB += fmaxf(l, 0.f) * w2r[2 * hp] + fmaxf(h, 0.f) * w2r[2 * hp + 1];
        }
        const int rA = rowbase + pass * 64;
        if (j2 == 0) {
            g_GL[(size_t)g * Bsz + rA]     = glA;
            g_GL[(size_t)g * Bsz + rA + 8] = glB;
        }
    }
}

// =======================================================================
// out init: out[b] = bp2[0]   (stage2 atomically accumulates onto this)
// =======================================================================
__global__ void out_init_kernel(const float* __restrict__ bp2,
                                float* __restrict__ out)
{
    int i = blockIdx.x * 256 + threadIdx.x;
    out[i] = bp2[0];
}

// =======================================================================
// Stage 2: register-tiled GEMM, PH split across 2 CTAs (pad 100->128,
//   each CTA owns 64 PH cols).  block = 128 (16 rowg x 8 cg),
//   thread tile = 4 rows x 8 cols (4 u64 acc).  MT2 = 64 rows.
//   grid = (B/64, 2).  Partial y added to out via atomicAdd (out preseeded
//   with bp2; exactly 2 deterministic contributions per row).
// =======================================================================
#define TH2    128
#define MT2    64
#define HCOLS  64            // PH cols per CTA (half of padded 128)
#define SMEM2_FLOATS (Gn * HCOLS + HCOLS + HCOLS + 8 * MT2)
#define SMEM2_BYTES  (SMEM2_FLOATS * 4)     // 35328

__global__ void __launch_bounds__(TH2)
stage2_kernel(const float* __restrict__ Wp1,
              const float* __restrict__ bp1,
              const float* __restrict__ Wp2,
              const float* __restrict__ bp2,
              float* __restrict__ out)
{
    extern __shared__ float sm[];
    float* wp   = sm;                    // [G][HCOLS] this ph-half, zero-padded
    float* bp1p = sm + Gn * HCOLS;       // [HCOLS]
    float* wp2p = bp1p + HCOLS;          // [HCOLS]
    float* part = wp2p + HCOLS;          // [8][MT2]

    const int tid = threadIdx.x;
    const int ph  = blockIdx.y;          // 0 or 1
    const int c0  = ph * HCOLS;          // global PH col base

    for (int i = tid; i < Gn * HCOLS; i += TH2) {
        int gg = i >> 6, c = (i & 63) + c0;
        wp[i] = (c < PHn) ? Wp1[gg * PHn + c] : 0.f;
    }
    if (tid < HCOLS) {
        int c = tid + c0;
        bp1p[tid] = (c < PHn) ? bp1[c] : 0.f;
        wp2p[tid] = (c < PHn) ? Wp2[c] : 0.f;
    }
    __syncthreads();

    const int rowg = tid & 15;          // 16 row-groups of 4 rows
    const int cg   = tid >> 4;          // 8 col-groups of 8 cols
    const int b0   = blockIdx.x * MT2 + rowg * 4;

    // accumulators seeded with bias (same for all 4 rows)
    ull acc[4][4];
    {
        const ull* bs = reinterpret_cast<const ull*>(bp1p + cg * 8);
#pragma unroll
        for (int q = 0; q < 4; q++) {
            ull v = bs[q];
#pragma unroll
            for (int r = 0; r < 4; r++) acc[r][q] = v;
        }
    }

    const float* glp = g_GL + b0;

#pragma unroll 1
    for (int g0 = 0; g0 < Gn; g0 += 4) {
        float4 gv[4];
#pragma unroll
        for (int j = 0; j < 4; j++)
            gv[j] = *reinterpret_cast<const float4*>(glp + (size_t)(g0 + j) * Bsz);

#pragma unroll
        for (int j = 0; j < 4; j++) {
            const ull* wr = reinterpret_cast<const ull*>(wp + (g0 + j) * HCOLS + cg * 8);
            ull wv[4];
#pragma unroll
            for (int q = 0; q < 4; q++) wv[q] = wr[q];   // 2x LDS.128 broadcast

            float gs[4] = {gv[j].x, gv[j].y, gv[j].z, gv[j].w};
#pragma unroll
            for (int r = 0; r < 4; r++) {
                ull a2 = dup2(gs[r]);
#pragma unroll
                for (int q = 0; q < 4; q++)
                    acc[r][q] = ffma2(a2, wv[q], acc[r][q]);
            }
        }
    }

    // epilogue: relu + dot with Wp2 slice, write partials
    {
        const ull* w2u = reinterpret_cast<const ull*>(wp2p + cg * 8);
        ull w2r[4];
#pragma unroll
        for (int q = 0; q < 4; q++) w2r[q] = w2u[q];
#pragma unroll
        for (int r = 0; r < 4; r++) {
            float y = 0.f;
#pragma unroll
            for (int q = 0; q < 4; q++) {
                float l, h, wl, wh;
                unpack2(acc[r][q], l, h);
                unpack2(w2r[q], wl, wh);
                y += fmaxf(l, 0.f) * wl + fmaxf(h, 0.f) * wh;
            }
            part[cg * MT2 + rowg * 4 + r] = y;
        }
    }
    __syncthreads();

    if (tid < MT2) {
        float s = part[tid];
#pragma unroll
        for (int c = 1; c < 8; c++) s += part[c * MT2 + tid];
        atomicAdd(&out[blockIdx.x * MT2 + tid], s);
    }
}

// =======================================================================
extern "C" void kernel_launch(void* const* d_in, const int* in_sizes, int n_in,
                              void* d_out, int out_size)
{
    const float* x   = (const float*)d_in[0];
    const float* W1  = (const float*)d_in[1];
    const float* b1  = (const float*)d_in[2];
    const float* W2  = (const float*)d_in[3];
    const float* b2  = (const float*)d_in[4];
    const float* Wp1 = (const float*)d_in[5];
    const float* bp1 = (const float*)d_in[6];
    const float* Wp2 = (const float*)d_in[7];
    const float* bp2 = (const float*)d_in[8];
    float* out = (float*)d_out;

    cudaFuncSetAttribute(stage2_kernel,
                         cudaFuncAttributeMaxDynamicSharedMemorySize, SMEM2_BYTES);

    dim3 grid1(Gn, Bsz / ROWS1);
    stage1_kernel<<<grid1, TH1>>>(x, W1, b1, W2, b2);
    out_init_kernel<<<Bsz / 256, 256>>>(bp2, out);
    dim3 grid2(Bsz / MT2, 2);
    stage2_kernel<<<grid2, TH2, SMEM2_BYTES>>>(Wp1, bp1, Wp2, bp2, out);
}

// round 16
// speedup vs baseline: 1.1072x; 1.0586x over previous
#include <cuda_runtime.h>
#include <cstdint>

#define Bsz  16384
#define Gn   128
#define Sn   64
#define Hn   10
#define PHn  100

typedef unsigned long long ull;

// scratch: gene_layer stored transposed [G][B]
__device__ float g_GL[(size_t)Gn * Bsz];

// ---------------- packed f32x2 helpers (sm_103a) ----------------
__device__ __forceinline__ ull ffma2(ull a, ull b, ull c) {
    ull d;
    asm("fma.rn.f32x2 %0, %1, %2, %3;" : "=l"(d) : "l"(a), "l"(b), "l"(c));
    return d;
}
__device__ __forceinline__ ull add2(ull a, ull b) {
    ull d;
    asm("add.rn.f32x2 %0, %1, %2;" : "=l"(d) : "l"(a), "l"(b));
    return d;
}
__device__ __forceinline__ ull dup2(float x) {
    ull r;
    asm("mov.b64 %0, {%1, %1};" : "=l"(r) : "f"(x));
    return r;
}
__device__ __forceinline__ void unpack2(ull v, float& lo, float& hi) {
    asm("mov.b64 {%0, %1}, %2;" : "=f"(lo), "=f"(hi) : "l"(v));
}

// =======================================================================
// Stage 1 v3: per-gene MLP.  4 lanes/row (j2 = lane&3 owns 4-SNP chunks),
//   4 rows/thread (rg, rg+8, rg+16, rg+24) -> W1 LDS amortized over 4 rows.
//   W1 smem rows padded to 6 u64 (16B-aligned) -> 2x LDS.128 + 1x LDS.64.
//   16 unrolled steps (4 passes x 4 k-chunks), prefetch 2 steps ahead.
//   grid = (G, B/ROWS1), block = 128
// =======================================================================
#define TH1     128
#define ROWS1   512

__global__ void __launch_bounds__(TH1)
stage1_kernel(const float* __restrict__ x,
              const float* __restrict__ W1,
              const float* __restrict__ b1,
              const float* __restrict__ W2,
              const float* __restrict__ b2)
{
    __shared__ ull  ws[4 * 98 + 8];     // [j2][ (k*4+i)*6 + hp ], stride 98
    __shared__ float w2s[10];
    __shared__ float b2s;

    const int g   = blockIdx.x;
    const int tid = threadIdx.x;

    // stage W1 pairs: pair p=(s,hp); s = 16k + 4j + i
    const ull* W1u = reinterpret_cast<const ull*>(W1 + (size_t)g * Sn * Hn);
    for (int p = tid; p < Sn * (Hn / 2); p += TH1) {   // 320 pairs
        int s = p / 5, hp = p % 5;
        int j = (s >> 2) & 3;
        int k = s >> 4;
        int i = s & 3;
        ws[j * 98 + (k * 4 + i) * 6 + hp] = W1u[p];
    }
    if (tid < 5)  ws[4 * 98 + tid] = reinterpret_cast<const ull*>(b1 + g * Hn)[tid];
    if (tid < 10) w2s[tid] = W2[g * Hn + tid];
    if (tid == 0) b2s = b2[g];
    __syncthreads();

    const int w    = tid >> 5;
    const int lane = tid & 31;
    const int rg   = lane >> 2;      // 0..7
    const int j2   = lane & 3;       // SNP-chunk slice
    const ull* wsl = ws + j2 * 98;

    ull b1r[5];
#pragma unroll
    for (int hp = 0; hp < 5; hp++) b1r[hp] = ws[4 * 98 + hp];
    float w2r[10];
#pragma unroll
    for (int h = 0; h < 10; h++) w2r[h] = w2s[h];
    const float b2v = b2s;

    // warp w covers rows [w*32, w*32+32) of each 128-row pass
    const int r0 = blockIdx.y * ROWS1 + w * 32 + rg;
    const float4* x4 = reinterpret_cast<const float4*>(x);
    // f4 index of (row r0+pass*128+m*8, gene g, chunk c=4k+j2):
    //   (r0+pass*128+m*8)*2048 + g*16 + 4k + j2
    const size_t gbase = (size_t)r0 * 2048 + (size_t)g * 16 + j2;
    // step t (0..15): pass=t>>2, k=t&3 ; offset = (t>>2)*262144 + (t&3)*4

    float4 buf[3][4];

    // prologue: steps 0,1
#pragma unroll
    for (int t = 0; t < 2; t++) {
        const size_t ip = gbase + (size_t)(t >> 2) * 262144 + (size_t)(t & 3) * 4;
#pragma unroll
        for (int m = 0; m < 4; m++) buf[t][m] = x4[ip + (size_t)m * 16384];
    }

    ull acc[4][5];

#pragma unroll
    for (int t = 0; t < 16; t++) {
        const int cur = t % 3;
        const int nxt = (t + 2) % 3;
        const int k   = t & 3;

        // prefetch step t+2
        if (t + 2 < 16) {
            const int t2 = t + 2;
            const size_t ip = gbase + (size_t)(t2 >> 2) * 262144 + (size_t)(t2 & 3) * 4;
#pragma unroll
            for (int m = 0; m < 4; m++) buf[nxt][m] = x4[ip + (size_t)m * 16384];
        }

        if (k == 0) {
#pragma unroll
            for (int m = 0; m < 4; m++)
#pragma unroll
                for (int hp = 0; hp < 5; hp++) acc[m][hp] = 0ull;
        }

        // compute chunk k: 4 SNPs (i=0..3) x 4 rows
#pragma unroll
        for (int i = 0; i < 4; i++) {
            const ull* wrow = wsl + (k * 4 + i) * 6;
            ulonglong2 w01 = *reinterpret_cast<const ulonglong2*>(wrow);
            ulonglong2 w23 = *reinterpret_cast<const ulonglong2*>(wrow + 2);
            ull        w4v = wrow[4];
#pragma unroll
            for (int m = 0; m < 4; m++) {
                float fv = (i == 0) ? buf[cur][m].x : (i == 1) ? buf[cur][m].y
                         : (i == 2) ? buf[cur][m].z : buf[cur][m].w;
                ull a2 = dup2(fv);
                acc[m][0] = ffma2(a2, w01.x, acc[m][0]);
                acc[m][1] = ffma2(a2, w01.y, acc[m][1]);
                acc[m][2] = ffma2(a2, w23.x, acc[m][2]);
                acc[m][3] = ffma2(a2, w23.y, acc[m][3]);
                acc[m][4] = ffma2(a2, w4v,   acc[m][4]);
            }
        }

        // pass boundary: reduce + epilogue
        if (k == 3) {
#pragma unroll
            for (int off = 1; off <= 2; off <<= 1) {
#pragma unroll
                for (int m = 0; m < 4; m++)
#pragma unroll
                    for (int hp = 0; hp < 5; hp++)
                        acc[m][hp] = add2(acc[m][hp],
                                          __shfl_xor_sync(0xffffffffu, acc[m][hp], off));
            }
#pragma unroll
            for (int m = 0; m < 4; m++) {
                float gl = b2v;
#pragma unroll
                for (int hp = 0; hp < 5; hp++) {
                    float l, h;
                    unpack2(add2(acc[m][hp], b1r[hp]), l, h);
                    gl += fmaxf(l, 0.f) * w2r[2 * hp] + fmaxf(h, 0.f) * w2r[2 * hp + 1];
                }
                if (j2 == 0)
                    g_GL[(size_t)g * Bsz + r0 + (t >> 2) * 128 + m * 8] = gl;
            }
        }
    }
}

// =======================================================================
// out init: out[b] = bp2[0]   (stage2 atomically accumulates onto this)
// =======================================================================
__global__ void out_init_kernel(const float* __restrict__ bp2,
                                float* __restrict__ out)
{
    int i = blockIdx.x * 256 + threadIdx.x;
    out[i] = bp2[0];
}

// =======================================================================
// Stage 2 (unchanged from R15): register-tiled GEMM, PH split across 2 CTAs.
//   block = 128 (16 rowg x 8 cg), thread tile 4 rows x 8 cols, MT2 = 64.
//   grid = (B/64, 2); partial y -> atomicAdd onto preseeded out.
// =======================================================================
#define TH2    128
#define MT2    64
#define HCOLS  64
#define SMEM2_FLOATS (Gn * HCOLS + HCOLS + HCOLS + 8 * MT2)
#define SMEM2_BYTES  (SMEM2_FLOATS * 4)

__global__ void __launch_bounds__(TH2)
stage2_kernel(const float* __restrict__ Wp1,
              const float* __restrict__ bp1,
              const float* __restrict__ Wp2,
              const float* __restrict__ bp2,
              float* __restrict__ out)
{
    extern __shared__ float sm[];
    float* wp   = sm;
    float* bp1p = sm + Gn * HCOLS;
    float* wp2p = bp1p + HCOLS;
    float* part = wp2p + HCOLS;

    const int tid = threadIdx.x;
    const int ph  = blockIdx.y;
    const int c0  = ph * HCOLS;

    for (int i = tid; i < Gn * HCOLS; i += TH2) {
        int gg = i >> 6, c = (i & 63) + c0;
        wp[i] = (c < PHn) ? Wp1[gg * PHn + c] : 0.f;
    }
    if (tid < HCOLS) {
        int c = tid + c0;
        bp1p[tid] = (c < PHn) ? bp1[c] : 0.f;
        wp2p[tid] = (c < PHn) ? Wp2[c] : 0.f;
    }
    __syncthreads();

    const int rowg = tid & 15;
    const int cg   = tid >> 4;
    const int b0   = blockIdx.x * MT2 + rowg * 4;

    ull acc[4][4];
    {
        const ull* bs = reinterpret_cast<const ull*>(bp1p + cg * 8);
#pragma unroll
        for (int q = 0; q < 4; q++) {
            ull v = bs[q];
#pragma unroll
            for (int r = 0; r < 4; r++) acc[r][q] = v;
        }
    }

    const float* glp = g_GL + b0;

#pragma unroll 1
    for (int g0 = 0; g0 < Gn; g0 += 4) {
        float4 gv[4];
#pragma unroll
        for (int j = 0; j < 4; j++)
            gv[j] = *reinterpret_cast<const float4*>(glp + (size_t)(g0 + j) * Bsz);

#pragma unroll
        for (int j = 0; j < 4; j++) {
            const ull* wr = reinterpret_cast<const ull*>(wp + (g0 + j) * HCOLS + cg * 8);
            ull wv[4];
#pragma unroll
            for (int q = 0; q < 4; q++) wv[q] = wr[q];

            float gs[4] = {gv[j].x, gv[j].y, gv[j].z, gv[j].w};
#pragma unroll
            for (int r = 0; r < 4; r++) {
                ull a2 = dup2(gs[r]);
#pragma unroll
                for (int q = 0; q < 4; q++)
                    acc[r][q] = ffma2(a2, wv[q], acc[r][q]);
            }
        }
    }

    {
        const ull* w2u = reinterpret_cast<const ull*>(wp2p + cg * 8);
        ull w2r[4];
#pragma unroll
        for (int q = 0; q < 4; q++) w2r[q] = w2u[q];
#pragma unroll
        for (int r = 0; r < 4; r++) {
            float y = 0.f;
#pragma unroll
            for (int q = 0; q < 4; q++) {
                float l, h, wl, wh;
                unpack2(acc[r][q], l, h);
                unpack2(w2r[q], wl, wh);
                y += fmaxf(l, 0.f) * wl + fmaxf(h, 0.f) * wh;
            }
            part[cg * MT2 + rowg * 4 + r] = y;
        }
    }
    __syncthreads();

    if (tid < MT2) {
        float s = part[tid];
#pragma unroll
        for (int c = 1; c < 8; c++) s += part[c * MT2 + tid];
        atomicAdd(&out[blockIdx.x * MT2 + tid], s);
    }
}

// =======================================================================
extern "C" void kernel_launch(void* const* d_in, const int* in_sizes, int n_in,
                              void* d_out, int out_size)
{
    const float* x   = (const float*)d_in[0];
    const float* W1  = (const float*)d_in[1];
    const float* b1  = (const float*)d_in[2];
    const float* W2  = (const float*)d_in[3];
    const float* b2  = (const float*)d_in[4];
    const float* Wp1 = (const float*)d_in[5];
    const float* bp1 = (const float*)d_in[6];
    const float* Wp2 = (const float*)d_in[7];
    const float* bp2 = (const float*)d_in[8];
    float* out = (float*)d_out;

    cudaFuncSetAttribute(stage2_kernel,
                         cudaFuncAttributeMaxDynamicSharedMemorySize, SMEM2_BYTES);

    dim3 grid1(Gn, Bsz / ROWS1);
    stage1_kernel<<<grid1, TH1>>>(x, W1, b1, W2, b2);
    out_init_kernel<<<Bsz / 256, 256>>>(bp2, out);
    dim3 grid2(Bsz / MT2, 2);
    stage2_kernel<<<grid2, TH2, SMEM2_BYTES>>>(Wp1, bp1, Wp2, bp2, out);
}

// round 17
// speedup vs baseline: 1.2389x; 1.1189x over previous
#include <cuda_runtime.h>
#include <cstdint>

#define Bsz  16384
#define Gn   128
#define Sn   64
#define Hn   10
#define PHn  100

typedef unsigned long long ull;

// scratch: gene_layer stored transposed [G][B]
__device__ float g_GL[(size_t)Gn * Bsz];

// ---------------- packed f32x2 helpers (sm_103a) ----------------
__device__ __forceinline__ ull ffma2(ull a, ull b, ull c) {
    ull d;
    asm("fma.rn.f32x2 %0, %1, %2, %3;" : "=l"(d) : "l"(a), "l"(b), "l"(c));
    return d;
}
__device__ __forceinline__ ull add2(ull a, ull b) {
    ull d;
    asm("add.rn.f32x2 %0, %1, %2;" : "=l"(d) : "l"(a), "l"(b));
    return d;
}
__device__ __forceinline__ ull dup2(float x) {
    ull r;
    asm("mov.b64 %0, {%1, %1};" : "=l"(r) : "f"(x));
    return r;
}
__device__ __forceinline__ void unpack2(ull v, float& lo, float& hi) {
    asm("mov.b64 {%0, %1}, %2;" : "=f"(lo), "=f"(hi) : "l"(v));
}

// =======================================================================
// Stage 1 v4: as v3 (4 lanes/row, 4 rows/thread, LDS.128 W1) but with
//   2 rotating buffers (depth-1 prefetch) + launch_bounds(128,4) so regs
//   fit 4 CTAs/SM (16 warps) instead of 3.
//   grid = (G, B/ROWS1), block = 128
// =======================================================================
#define TH1     128
#define ROWS1   512

__global__ void __launch_bounds__(TH1, 4)
stage1_kernel(const float* __restrict__ x,
              const float* __restrict__ W1,
              const float* __restrict__ b1,
              const float* __restrict__ W2,
              const float* __restrict__ b2)
{
    __shared__ ull  ws[4 * 98 + 8];     // [j2][ (k*4+i)*6 + hp ], stride 98
    __shared__ float w2s[10];
    __shared__ float b2s;

    const int g   = blockIdx.x;
    const int tid = threadIdx.x;

    const ull* W1u = reinterpret_cast<const ull*>(W1 + (size_t)g * Sn * Hn);
    for (int p = tid; p < Sn * (Hn / 2); p += TH1) {   // 320 pairs
        int s = p / 5, hp = p % 5;
        int j = (s >> 2) & 3;
        int k = s >> 4;
        int i = s & 3;
        ws[j * 98 + (k * 4 + i) * 6 + hp] = W1u[p];
    }
    if (tid < 5)  ws[4 * 98 + tid] = reinterpret_cast<const ull*>(b1 + g * Hn)[tid];
    if (tid < 10) w2s[tid] = W2[g * Hn + tid];
    if (tid == 0) b2s = b2[g];
    __syncthreads();

    const int w    = tid >> 5;
    const int lane = tid & 31;
    const int rg   = lane >> 2;      // 0..7
    const int j2   = lane & 3;       // SNP-chunk slice
    const ull* wsl = ws + j2 * 98;

    ull b1r[5];
#pragma unroll
    for (int hp = 0; hp < 5; hp++) b1r[hp] = ws[4 * 98 + hp];
    float w2r[10];
#pragma unroll
    for (int h = 0; h < 10; h++) w2r[h] = w2s[h];
    const float b2v = b2s;

    const int r0 = blockIdx.y * ROWS1 + w * 32 + rg;
    const float4* x4 = reinterpret_cast<const float4*>(x);
    const size_t gbase = (size_t)r0 * 2048 + (size_t)g * 16 + j2;
    // step t (0..15): pass=t>>2, k=t&3 ; f4 offset = (t>>2)*262144 + (t&3)*4

    float4 buf[2][4];

    // prologue: step 0
#pragma unroll
    for (int m = 0; m < 4; m++) buf[0][m] = x4[gbase + (size_t)m * 16384];

    ull acc[4][5];

#pragma unroll
    for (int t = 0; t < 16; t++) {
        const int cur = t & 1;
        const int nxt = cur ^ 1;
        const int k   = t & 3;

        // prefetch step t+1
        if (t + 1 < 16) {
            const int t1 = t + 1;
            const size_t ip = gbase + (size_t)(t1 >> 2) * 262144 + (size_t)(t1 & 3) * 4;
#pragma unroll
            for (int m = 0; m < 4; m++) buf[nxt][m] = x4[ip + (size_t)m * 16384];
        }

        if (k == 0) {
#pragma unroll
            for (int m = 0; m < 4; m++)
#pragma unroll
                for (int hp = 0; hp < 5; hp++) acc[m][hp] = 0ull;
        }

        // compute chunk k: 4 SNPs (i) x 4 rows (m)
#pragma unroll
        for (int i = 0; i < 4; i++) {
            const ull* wrow = wsl + (k * 4 + i) * 6;
            ulonglong2 w01 = *reinterpret_cast<const ulonglong2*>(wrow);
            ulonglong2 w23 = *reinterpret_cast<const ulonglong2*>(wrow + 2);
            ull        w4v = wrow[4];
#pragma unroll
            for (int m = 0; m < 4; m++) {
                float fv = (i == 0) ? buf[cur][m].x : (i == 1) ? buf[cur][m].y
                         : (i == 2) ? buf[cur][m].z : buf[cur][m].w;
                ull a2 = dup2(fv);
                acc[m][0] = ffma2(a2, w01.x, acc[m][0]);
                acc[m][1] = ffma2(a2, w01.y, acc[m][1]);
                acc[m][2] = ffma2(a2, w23.x, acc[m][2]);
                acc[m][3] = ffma2(a2, w23.y, acc[m][3]);
                acc[m][4] = ffma2(a2, w4v,   acc[m][4]);
            }
        }

        // pass boundary: reduce + epilogue
        if (k == 3) {
#pragma unroll
            for (int off = 1; off <= 2; off <<= 1) {
#pragma unroll
                for (int m = 0; m < 4; m++)
#pragma unroll
                    for (int hp = 0; hp < 5; hp++)
                        acc[m][hp] = add2(acc[m][hp],
                                          __shfl_xor_sync(0xffffffffu, acc[m][hp], off));
            }
#pragma unroll
            for (int m = 0; m < 4; m++) {
                float gl = b2v;
#pragma unroll
                for (int hp = 0; hp < 5; hp++) {
                    float l, h;
                    unpack2(add2(acc[m][hp], b1r[hp]), l, h);
                    gl += fmaxf(l, 0.f) * w2r[2 * hp] + fmaxf(h, 0.f) * w2r[2 * hp + 1];
                }
                if (j2 == 0)
                    g_GL[(size_t)g * Bsz + r0 + (t >> 2) * 128 + m * 8] = gl;
            }
        }
    }
}

// =======================================================================
// out init: out[b] = bp2[0]   (stage2 atomically accumulates onto this)
// =======================================================================
__global__ void out_init_kernel(const float* __restrict__ bp2,
                                float* __restrict__ out)
{
    int i = blockIdx.x * 256 + threadIdx.x;
    out[i] = bp2[0];
}

// =======================================================================
// Stage 2: register-tiled GEMM, PH split across 2 CTAs, 8-gene chunks
//   (8 back-to-back gl LDG.128 -> MLP 8).  block = 128 (16 rowg x 8 cg),
//   thread tile 4 rows x 8 cols, MT2 = 64.  grid = (B/64, 2);
//   partial y -> atomicAdd onto preseeded out.
// =======================================================================
#define TH2    128
#define MT2    64
#define HCOLS  64
#define SMEM2_FLOATS (Gn * HCOLS + HCOLS + HCOLS + 8 * MT2)
#define SMEM2_BYTES  (SMEM2_FLOATS * 4)

__global__ void __launch_bounds__(TH2)
stage2_kernel(const float* __restrict__ Wp1,
              const float* __restrict__ bp1,
              const float* __restrict__ Wp2,
              const float* __restrict__ bp2,
              float* __restrict__ out)
{
    extern __shared__ float sm[];
    float* wp   = sm;
    float* bp1p = sm + Gn * HCOLS;
    float* wp2p = bp1p + HCOLS;
    float* part = wp2p + HCOLS;

    const int tid = threadIdx.x;
    const int ph  = blockIdx.y;
    const int c0  = ph * HCOLS;

    for (int i = tid; i < Gn * HCOLS; i += TH2) {
        int gg = i >> 6, c = (i & 63) + c0;
        wp[i] = (c < PHn) ? Wp1[gg * PHn + c] : 0.f;
    }
    if (tid < HCOLS) {
        int c = tid + c0;
        bp1p[tid] = (c < PHn) ? bp1[c] : 0.f;
        wp2p[tid] = (c < PHn) ? Wp2[c] : 0.f;
    }
    __syncthreads();

    const int rowg = tid & 15;
    const int cg   = tid >> 4;
    const int b0   = blockIdx.x * MT2 + rowg * 4;

    ull acc[4][4];
    {
        const ull* bs = reinterpret_cast<const ull*>(bp1p + cg * 8);
#pragma unroll
        for (int q = 0; q < 4; q++) {
            ull v = bs[q];
#pragma unroll
            for (int r = 0; r < 4; r++) acc[r][q] = v;
        }
    }

    const float* glp = g_GL + b0;

#pragma unroll 1
    for (int g0 = 0; g0 < Gn; g0 += 8) {
        float4 gv[8];
#pragma unroll
        for (int j = 0; j < 8; j++)
            gv[j] = *reinterpret_cast<const float4*>(glp + (size_t)(g0 + j) * Bsz);

#pragma unroll
        for (int j = 0; j < 8; j++) {
            const ull* wr = reinterpret_cast<const ull*>(wp + (g0 + j) * HCOLS + cg * 8);
            ull wv[4];
#pragma unroll
            for (int q = 0; q < 4; q++) wv[q] = wr[q];   // 2x LDS.128 broadcast

            float gs[4] = {gv[j].x, gv[j].y, gv[j].z, gv[j].w};
#pragma unroll
            for (int r = 0; r < 4; r++) {
                ull a2 = dup2(gs[r]);
#pragma unroll
                for (int q = 0; q < 4; q++)
                    acc[r][q] = ffma2(a2, wv[q], acc[r][q]);
            }
        }
    }

    {
        const ull* w2u = reinterpret_cast<const ull*>(wp2p + cg * 8);
        ull w2r[4];
#pragma unroll
        for (int q = 0; q < 4; q++) w2r[q] = w2u[q];
#pragma unroll
        for (int r = 0; r < 4; r++) {
            float y = 0.f;
#pragma unroll
            for (int q = 0; q < 4; q++) {
                float l, h, wl, wh;
                unpack2(acc[r][q], l, h);
                unpack2(w2r[q], wl, wh);
                y += fmaxf(l, 0.f) * wl + fmaxf(h, 0.f) * wh;
            }
            part[cg * MT2 + rowg * 4 + r] = y;
        }
    }
    __syncthreads();

    if (tid < MT2) {
        float s = part[tid];
#pragma unroll
        for (int c = 1; c < 8; c++) s += part[c * MT2 + tid];
        atomicAdd(&out[blockIdx.x * MT2 + tid], s);
    }
}

// =======================================================================
extern "C" void kernel_launch(void* const* d_in, const int* in_sizes, int n_in,
                              void* d_out, int out_size)
{
    const float* x   = (const float*)d_in[0];
    const float* W1  = (const float*)d_in[1];
    const float* b1  = (const float*)d_in[2];
    const float* W2  = (const float*)d_in[3];
    const float* b2  = (const float*)d_in[4];
    const float* Wp1 = (const float*)d_in[5];
    const float* bp1 = (const float*)d_in[6];
    const float* Wp2 = (const float*)d_in[7];
    const float* bp2 = (const float*)d_in[8];
    float* out = (float*)d_out;

    cudaFuncSetAttribute(stage2_kernel,
                         cudaFuncAttributeMaxDynamicSharedMemorySize, SMEM2_BYTES);

    dim3 grid1(Gn, Bsz / ROWS1);
    stage1_kernel<<<grid1, TH1>>>(x, W1, b1, W2, b2);
    out_init_kernel<<<Bsz / 256, 256>>>(bp2, out);
    dim3 grid2(Bsz / MT2, 2);
    stage2_kernel<<<grid2, TH2, SMEM2_BYTES>>>(Wp1, bp1, Wp2, bp2, out);
}